// round 16
// baseline (speedup 1.0000x reference)
#include <cuda_runtime.h>
#include <cuda_fp16.h>
#include <math.h>

#define BB 32
#define SS 256
#define TT 256
#define HH 4096
#define EE 64
#define EPS_V 1e-6f
#define CHUNK 512      // h per k_out2 block (thread owns 4 h)
#define TTILE 8        // t per k_out2 block
#define NBH (BB / 2)   // b per k_out2 block (z-split)
#define SMEM_OUT2 (EE * CHUNK * 2 + 2048 + 2048)  // 64KB experts + wh + ix

// ---------------- scratch (no allocations allowed) ----------------
__device__ float g_m[BB * HH];        // sum over s of input_embeds  (512 KB)
__device__ float g_cond[BB * EE];     // cond[:, :E]                 (8 KB)
__device__ float4 g_w[BB * TT];       // top-4 weights, pre-scaled by (1-g)
__device__ int4 g_idx[BB * TT];       // top-4 expert indices
__device__ float g_pbmax[EE];         // per-e max_t pb[t,e]
__device__ float g_pbmin[EE];         // per-e min_t pb[t,e]
__device__ float g_pdmax[EE];         // per-e max_t |pd[t,e]|

__device__ __forceinline__ __half2 u2h2(unsigned int u) {
    return *reinterpret_cast<__half2*>(&u);
}
__device__ __forceinline__ unsigned int h22u(__half2 h) {
    return *reinterpret_cast<unsigned int*>(&h);
}

// ---------------- K1: m[b,h] = sum_s x[b,s,h]  (+ hidden pb/pd stat block) ----------------
__global__ __launch_bounds__(256) void k_reduce_s(const float* __restrict__ x,
                                                  const float* __restrict__ pb,
                                                  const float* __restrict__ pd) {
    int bx = blockIdx.x, b = blockIdx.y;
    int tid = threadIdx.x;

    if (bx == HH / 256) {
        if (b != 0) return;
        __shared__ float s_mx[4][EE], s_mn[4][EE], s_dm[4][EE];
        int e = tid & 63, q = tid >> 6;
        float mx = -3.4e38f, mn = 3.4e38f, dm = 0.f;
#pragma unroll 8
        for (int k = 0; k < 64; ++k) {
            int t = q * 64 + k;
            float p = pb[t * HH + e];
            float d = pd[t * HH + e];
            mx = fmaxf(mx, p);
            mn = fminf(mn, p);
            dm = fmaxf(dm, fabsf(d));
        }
        s_mx[q][e] = mx; s_mn[q][e] = mn; s_dm[q][e] = dm;
        __syncthreads();
        if (q == 0) {
#pragma unroll
            for (int j = 1; j < 4; ++j) {
                mx = fmaxf(mx, s_mx[j][e]);
                mn = fminf(mn, s_mn[j][e]);
                dm = fmaxf(dm, s_dm[j][e]);
            }
            g_pbmax[e] = mx;
            g_pbmin[e] = mn;
            g_pdmax[e] = dm;
        }
        return;
    }

    int h = bx * 256 + tid;
    const float* p = x + (size_t)b * SS * HH + h;
    float acc = 0.f;
#pragma unroll 16
    for (int s = 0; s < SS; ++s) acc += p[(size_t)s * HH];
    g_m[b * HH + h] = acc;
}

// ---------------- K2: cond[b,e] = (1/S) * sum_h m[b,h]*W[e,h], e < E ----------------
__global__ __launch_bounds__(256) void k_cond(const float* __restrict__ W) {
    int e = blockIdx.x;
    int bg = blockIdx.y * 2;
    int tid = threadIdx.x;
    const float4* w = (const float4*)(W + (size_t)e * HH);
    const float4* m0 = (const float4*)(g_m + (size_t)bg * HH);
    const float4* m1 = (const float4*)(g_m + (size_t)(bg + 1) * HH);

    float a0 = 0.f, a1 = 0.f;
#pragma unroll
    for (int i = tid; i < HH / 4; i += 256) {
        float4 wv = __ldg(w + i);
        float4 v0 = m0[i];
        float4 v1 = m1[i];
        a0 += wv.x * v0.x + wv.y * v0.y + wv.z * v0.z + wv.w * v0.w;
        a1 += wv.x * v1.x + wv.y * v1.y + wv.z * v1.z + wv.w * v1.w;
    }
#pragma unroll
    for (int o = 16; o > 0; o >>= 1) {
        a0 += __shfl_down_sync(0xffffffffu, a0, o);
        a1 += __shfl_down_sync(0xffffffffu, a1, o);
    }
    __shared__ float sred[2][8];
    int warp = tid >> 5, lane = tid & 31;
    if (lane == 0) {
        sred[0][warp] = a0;
        sred[1][warp] = a1;
    }
    __syncthreads();
    if (tid < 2) {
        float v = 0.f;
#pragma unroll
        for (int j = 0; j < 8; ++j) v += sred[tid][j];
        g_cond[(bg + tid) * EE + e] = v * (1.0f / SS);
    }
}

// ---------------- K3: scales (exact decomposition) + top-4 + weights ----------------
__global__ __launch_bounds__(256) void k_weights(const float* __restrict__ pb,
                                                 const float* __restrict__ pd,
                                                 const float* __restrict__ gamma) {
    int e = threadIdx.x;   // 0..63
    int ty = threadIdx.y;  // 0..3
    int t = blockIdx.x * 4 + ty;
    int b = blockIdx.y;

    __shared__ float s_cmx[4][EE], s_cmn[4][EE];
    __shared__ float s_h[EE], s_d[EE];
    __shared__ float s_scl[2];
    __shared__ float s_log[4][EE];
    __shared__ float s_val[4][4];
    __shared__ int s_ix[4][4];

    {
        float cmx = -3.4e38f, cmn = 3.4e38f;
#pragma unroll
        for (int j = 0; j < 8; ++j) {
            float c = g_cond[(ty * 8 + j) * EE + e];
            cmx = fmaxf(cmx, c);
            cmn = fminf(cmn, c);
        }
        s_cmx[ty][e] = cmx;
        s_cmn[ty][e] = cmn;
        __syncthreads();
        if (ty == 0) {
#pragma unroll
            for (int j = 1; j < 4; ++j) {
                cmx = fmaxf(cmx, s_cmx[j][e]);
                cmn = fminf(cmn, s_cmn[j][e]);
            }
            s_h[e] = fmaxf(g_pbmax[e] + cmx, -(g_pbmin[e] + cmn));
            s_d[e] = g_pdmax[e];
        }
        __syncthreads();
        if (ty == 0 && e < 32) {
            float hv = fmaxf(s_h[e], s_h[e + 32]);
            float dv = fmaxf(s_d[e], s_d[e + 32]);
#pragma unroll
            for (int o = 16; o > 0; o >>= 1) {
                hv = fmaxf(hv, __shfl_down_sync(0xffffffffu, hv, o));
                dv = fmaxf(dv, __shfl_down_sync(0xffffffffu, dv, o));
            }
            if (e == 0) {
                s_scl[0] = 1.f / fmaxf(hv, EPS_V);
                s_scl[1] = 1.f / fmaxf(dv, EPS_V);
            }
        }
        __syncthreads();
    }
    float invHs = s_scl[0], invDs = s_scl[1];

    float v = 0.5f * (pb[t * HH + e] + g_cond[b * EE + e]) * invHs +
              0.5f * pd[t * HH + e] * invDs;
    s_log[ty][e] = v;
    __syncthreads();

    int rank = 0;
#pragma unroll
    for (int j = 0; j < EE; ++j) {
        float u = s_log[ty][j];
        rank += (u > v) || (u == v && j < e);
    }
    if (rank < 4) {
        s_val[ty][rank] = v;
        s_ix[ty][rank] = e;
    }
    __syncthreads();

    if (e == 0) {
        float bv0 = s_val[ty][0], bv1 = s_val[ty][1];
        float bv2 = s_val[ty][2], bv3 = s_val[ty][3];
        float e1 = __expf(bv1 - bv0);
        float e2 = __expf(bv2 - bv0);
        float e3 = __expf(bv3 - bv0);
        float g = 1.f / (1.f + __expf(-gamma[0]));
        float scale = (1.f - g) / (1.0f + e1 + e2 + e3);
        g_w[b * TT + t] = make_float4(scale, e1 * scale, e2 * scale, e3 * scale);
        g_idx[b * TT + t] = make_int4(s_ix[ty][0], s_ix[ty][1], s_ix[ty][2], s_ix[ty][3]);
    }
}

// ---------------- K4: output, half2 dot, 4h/thread, Sum(w)=(1-g) folded ----------------
// mix = (1-g) + g*shv + sum_k w_k*u_k  (u = lime-1 in half2; w as broadcast
// half2; dot via HFMA2). Per 4 outputs: ~2 LDS.128 meta + 4 LDS.64 gathers +
// 8 HFMA2 + 4 cvt + 8 fp32 + 1 STG.128 (~8 instr/output vs 17 before).
// grid (HH/512, TT/8, 2) = 512 blocks; block 128; smem 68KB -> 3 blocks/SM.
__global__ __launch_bounds__(128) void k_out2(const float* __restrict__ pb,
                                              const float* __restrict__ pd,
                                              const float* __restrict__ limes,
                                              const float* __restrict__ shv,
                                              const float* __restrict__ gamma,
                                              float* __restrict__ out) {
    extern __shared__ char dsm[];
    __half2* s_u = (__half2*)dsm;                           // [EE][CHUNK/2], 64 KB
    uint4* s_wh = (uint4*)(dsm + EE * CHUNK * 2);           // 128 recs, 2 KB
    int4* s_ixr = (int4*)(dsm + EE * CHUNK * 2 + 2048);     // 128 recs, 2 KB

    int chunk = blockIdx.x, ttile = blockIdx.y;
    int b0 = blockIdx.z * NBH;
    int tid = threadIdx.x;                                  // 0..127, owns 4 h
    int base = chunk * CHUNK;
    int tbase = ttile * TTILE;

    // stage residual experts u = lime - 1 as half2 (row e = iteration k)
#pragma unroll 4
    for (int k = 0; k < EE; ++k) {
        float4 v = ((const float4*)(limes + (size_t)k * HH + base))[tid];
        __half2 lo = __floats2half2_rn(v.x - 1.0f, v.y - 1.0f);
        __half2 hi = __floats2half2_rn(v.z - 1.0f, v.w - 1.0f);
        ((uint2*)(s_u + (size_t)k * (CHUNK / 2)))[tid] = make_uint2(h22u(lo), h22u(hi));
    }
    // stage weight records: 128 recs = NBH(16) x TTILE(8), one per thread.
    // weights as broadcast half2; indices pre-scaled to uint2 units (CHUNK/4).
    {
        int b = b0 + (tid >> 3), j = tid & 7;
        float4 w = g_w[b * TT + tbase + j];
        int4 ix = g_idx[b * TT + tbase + j];
        s_wh[tid] = make_uint4(h22u(__float2half2_rn(w.x)), h22u(__float2half2_rn(w.y)),
                               h22u(__float2half2_rn(w.z)), h22u(__float2half2_rn(w.w)));
        s_ixr[tid] = make_int4(ix.x * (CHUNK / 4), ix.y * (CHUNK / 4),
                               ix.z * (CHUNK / 4), ix.w * (CHUNK / 4));
    }

    // pb+pd tile into registers (one-time read, reused for 16 b)
    float4 p[TTILE];
#pragma unroll
    for (int j = 0; j < TTILE; ++j) {
        float4 a = ((const float4*)(pb + (size_t)(tbase + j) * HH + base))[tid];
        float4 c = ((const float4*)(pd + (size_t)(tbase + j) * HH + base))[tid];
        p[j] = make_float4(a.x + c.x, a.y + c.y, a.z + c.z, a.w + c.w);
    }

    float g = 1.f / (1.f + __expf(-gamma[0]));
    float4 sh = ((const float4*)(shv + base))[tid];
    float4 bs = make_float4((1.f - g) + g * sh.x, (1.f - g) + g * sh.y,
                            (1.f - g) + g * sh.z, (1.f - g) + g * sh.w);
    __syncthreads();

    const uint2* U = (const uint2*)s_u;
    for (int bb = 0; bb < NBH; ++bb) {
        int b = b0 + bb;
        float* O = out + ((size_t)b * TT + tbase) * HH + base + 4 * tid;
#pragma unroll
        for (int j = 0; j < TTILE; ++j) {
            int r = bb * TTILE + j;
            uint4 wh = s_wh[r];
            int4 ix = s_ixr[r];
            uint2 u0 = U[ix.x + tid];
            uint2 u1 = U[ix.y + tid];
            uint2 u2 = U[ix.z + tid];
            uint2 u3 = U[ix.w + tid];
            __half2 dlo = __hmul2(u2h2(wh.x), u2h2(u0.x));
            dlo = __hfma2(u2h2(wh.y), u2h2(u1.x), dlo);
            dlo = __hfma2(u2h2(wh.z), u2h2(u2.x), dlo);
            dlo = __hfma2(u2h2(wh.w), u2h2(u3.x), dlo);
            __half2 dhi = __hmul2(u2h2(wh.x), u2h2(u0.y));
            dhi = __hfma2(u2h2(wh.y), u2h2(u1.y), dhi);
            dhi = __hfma2(u2h2(wh.z), u2h2(u2.y), dhi);
            dhi = __hfma2(u2h2(wh.w), u2h2(u3.y), dhi);
            float2 flo = __half22float2(dlo);
            float2 fhi = __half22float2(dhi);
            float4 res;
            res.x = p[j].x * (bs.x + flo.x);
            res.y = p[j].y * (bs.y + flo.y);
            res.z = p[j].z * (bs.z + fhi.x);
            res.w = p[j].w * (bs.w + fhi.y);
            __stcs((float4*)(O + (size_t)j * HH), res);
        }
    }
}

extern "C" void kernel_launch(void* const* d_in, const int* in_sizes, int n_in,
                              void* d_out, int out_size) {
    const float* x     = (const float*)d_in[0];  // input_embeds (B,S,H)
    const float* pb    = (const float*)d_in[1];  // prompt_base  (T,H)
    const float* pd    = (const float*)d_in[2];  // prompt_delta (T,H)
    const float* limes = (const float*)d_in[3];  // LiMEs        (E,H)
    const float* shv   = (const float*)d_in[4];  // LiME_shared  (H,)
    const float* gamma = (const float*)d_in[5];  // gamma        (1,)
    const float* W     = (const float*)d_in[6];  // W_proj       (H,H)
    float* out = (float*)d_out;                  // (B,T,H) f32

    static bool attr_set = false;
    if (!attr_set) {
        cudaFuncSetAttribute(k_out2, cudaFuncAttributeMaxDynamicSharedMemorySize, SMEM_OUT2);
        attr_set = true;
    }

    k_reduce_s<<<dim3(HH / 256 + 1, BB), 256>>>(x, pb, pd);
    k_cond<<<dim3(EE, BB / 2), 256>>>(W);
    k_weights<<<dim3(TT / 4, BB), dim3(64, 4)>>>(pb, pd, gamma);
    k_out2<<<dim3(HH / CHUNK, TT / TTILE, 2), 128, SMEM_OUT2>>>(pb, pd, limes, shv, gamma, out);
}